// round 7
// baseline (speedup 1.0000x reference)
#include <cuda_runtime.h>
#include <cuda_bf16.h>

#define NBINS 10
#define TPB 256

// Global scratch (no device allocation allowed). Zero-initialized at module
// load; last block resets after finalize; atomicInc wrap resets g_done.
__device__ float g_sums[NBINS];
__device__ float g_cnts[NBINS];
__device__ unsigned int g_done;

__global__ __launch_bounds__(TPB, 6) void ghmc_fused(
    const float4* __restrict__ pred4,
    const int4*   __restrict__ targ4,
    const float4* __restrict__ lw4,
    int n4,
    float* __restrict__ out)
{
    // Per-THREAD private histogram slots: hist[bin][tid] = (sum, count).
    // [bin][tid] layout -> lane l always hits banks 2l,2l+1: conflict-free.
    __shared__ float2 hist[NBINS][TPB];   // 20 KB

    const int tid = threadIdx.x;

#pragma unroll
    for (int b = 0; b < NBINS; b++)
        hist[b][tid] = make_float2(0.0f, 0.0f);
    // No sync needed: slots are thread-private until the fold.

    const int stride = gridDim.x * blockDim.x;

    for (int i = blockIdx.x * blockDim.x + tid; i < n4; i += 2 * stride) {
        // Front-batch BOTH iterations' loads (6 outstanding LDG.128).
        int j = i + stride;
        bool has2 = j < n4;
        int jc = has2 ? j : (n4 - 1);

        float4 p0 = __ldcs(pred4 + i);
        int4   t0 = __ldcs(targ4 + i);
        float4 w0 = __ldcs(lw4 + i);
        float4 p1 = __ldcs(pred4 + jc);
        int4   t1 = __ldcs(targ4 + jc);
        float4 w1 = __ldcs(lw4 + jc);

        if (!has2) w1 = make_float4(0.0f, 0.0f, 0.0f, 0.0f);  // -> (0,0) adds

        float px[8] = {p0.x, p0.y, p0.z, p0.w, p1.x, p1.y, p1.z, p1.w};
        int   tx[8] = {t0.x, t0.y, t0.z, t0.w, t1.x, t1.y, t1.z, t1.w};
        float wx[8] = {w0.x, w0.y, w0.z, w0.w, w1.x, w1.y, w1.z, w1.w};

#pragma unroll
        for (int k = 0; k < 8; k++) {
            float x  = px[k];
            int   ti = tx[k];
            bool  valid = wx[k] > 0.0f;

            // e = exp(-|x|) via exp2 (fabs/neg fold into operand modifiers)
            float e = exp2f(-1.44269504f * fabsf(x));
            float r = __fdividef(1.0f, 1.0f + e);   // sigmoid(|x|)

            // g = |sigmoid(x) - t| = sigmoid(x*(1-2t))
            float xp = (ti != 0) ? -x : x;
            float g  = (xp >= 0.0f) ? r : e * r;

            int bin = min((int)(g * 10.0f), NBINS - 1);

            // bce = max(x,0) - x*t + log1p(e);  log(1+e) = -ln2*log2(r)
            float bce = fmaf(-x, (float)ti, fmaxf(x, 0.0f));
            bce = fmaf(-0.69314718f, __log2f(r), bce);

            float v  = valid ? bce  : 0.0f;   // invalid adds (0,0): branchless
            float cf = valid ? 1.0f : 0.0f;

            float2 acc = hist[bin][tid];      // LDS.64
            acc.x += v;
            acc.y += cf;
            hist[bin][tid] = acc;             // STS.64
        }
    }
    __syncthreads();

    // In-smem tree fold over the 256 thread columns (counts stay f32-exact).
#pragma unroll
    for (int off = TPB / 2; off > 0; off >>= 1) {
        if (tid < off) {
#pragma unroll
            for (int b = 0; b < NBINS; b++) {
                float2 a = hist[b][tid];
                float2 o = hist[b][tid + off];
                hist[b][tid] = make_float2(a.x + o.x, a.y + o.y);
            }
        }
        __syncthreads();
    }

    if (tid < NBINS) {
        atomicAdd(&g_sums[tid], hist[tid][0].x);
        atomicAdd(&g_cnts[tid], hist[tid][0].y);
    }

    // --- last-block finalize (threadfence reduction pattern) ---
    __shared__ bool is_last;
    if (tid == 0) {
        __threadfence();
        unsigned r = atomicInc(&g_done, gridDim.x - 1);  // wraps to 0 on last
        is_last = (r == gridDim.x - 1);
    }
    __syncthreads();

    if (is_last && tid < 32) {
        __threadfence();
        float contrib = 0.0f;
        float nb = 0.0f;
        if (tid < NBINS) {
            float cb = __ldcg(&g_cnts[tid]);
            float sb = __ldcg(&g_sums[tid]);
            contrib = sb / fmaxf(cb, 1.0f);   // empty bin: sb==0 -> 0
            nb = (cb > 0.0f) ? 1.0f : 0.0f;
            g_cnts[tid] = 0.0f;               // reset for next graph replay
            g_sums[tid] = 0.0f;
        }
#pragma unroll
        for (int o = 16; o > 0; o >>= 1) {
            contrib += __shfl_down_sync(0xffffffffu, contrib, o);
            nb      += __shfl_down_sync(0xffffffffu, nb, o);
        }
        if (tid == 0)
            out[0] = contrib / fmaxf(nb, 1.0f);   // LOSS_WEIGHT = 1.0
    }
}

extern "C" void kernel_launch(void* const* d_in, const int* in_sizes, int n_in,
                              void* d_out, int out_size) {
    const float4* pred4 = (const float4*)d_in[0];
    const int4*   targ4 = (const int4*)d_in[1];
    const float4* lw4   = (const float4*)d_in[2];
    float* out = (float*)d_out;

    int n  = in_sizes[0];
    int n4 = n >> 2;   // 67,108,864 / 4 = 16,777,216

    // 148 SMs x 6 resident blocks (20KB smem, ~40 regs) -> one exact wave.
    ghmc_fused<<<888, TPB>>>(pred4, targ4, lw4, n4, out);
}